// round 2
// baseline (speedup 1.0000x reference)
#include <cuda_runtime.h>
#include <cstdint>

// Problem constants
#define B_      16
#define C_      512
#define HW_     16384
#define K_      19          // classes
#define IGN     255
#define NPIX    (B_ * HW_)  // 262144

// Main-kernel tiling
#define CTILES      (C_ / 16)   // 32 channel tiles of 16
#define SPLITS      8           // pixel splits -> 2048 px per CTA
#define PX_CTA      (HW_ / SPLITS)      // 2048
#define STAGE_PX    256                 // pixels staged per stage
#define NSTAGES     (PX_CTA / STAGE_PX) // 8
#define ROWPAD      260                 // 256 + 4 floats pad -> conflict-free LDS

// ---------------- device scratch (no allocations allowed) ----------------
__device__ int            g_is64;
__device__ unsigned char  g_lbl8[NPIX];
__device__ int            g_counts[B_ * K_];
__device__ float          g_scratch[B_ * C_ * K_];

// ---------------- helpers ----------------
__device__ __forceinline__ uint32_t smem_u32(const void* p) {
    uint32_t a;
    asm("{ .reg .u64 t; cvta.to.shared.u64 t, %1; cvt.u32.u64 %0, t; }"
        : "=r"(a) : "l"(p));
    return a;
}

// ---------------- K1: dtype detect + zero scratch/counts ----------------
__global__ void k_prep0(const int* __restrict__ lblraw) {
    int tid = blockIdx.x * blockDim.x + threadIdx.x;
    int stride = gridDim.x * blockDim.x;

    if (blockIdx.x == 0) {
        // If labels are int64 (little-endian, values 0..18), every odd 32-bit
        // word of the first 512 elements is 0. For int32 labels the odd words
        // are labels themselves: P(all 512 == 0) = (1/19)^512 ~ 0.
        __shared__ int s_ok;
        if (threadIdx.x == 0) s_ok = 1;
        __syncthreads();
        int bad = 0;
        for (int i = threadIdx.x; i < 512; i += blockDim.x)
            if (lblraw[2 * i + 1] != 0) bad = 1;
        if (bad) atomicAnd(&s_ok, 0);
        __syncthreads();
        if (threadIdx.x == 0) g_is64 = s_ok;
    }

    for (int i = tid; i < B_ * C_ * K_; i += stride) g_scratch[i] = 0.0f;
    for (int i = tid; i < B_ * K_;      i += stride) g_counts[i]  = 0;
}

// ---------------- K2: build u8 labels + per-(b,k) counts ----------------
// One block per 256 pixels; 256 | HW_ so a block stays within one batch b.
__global__ void k_prep1(const int* __restrict__ lblraw) {
    __shared__ int scnt[K_];
    int t = threadIdx.x;
    if (t < K_) scnt[t] = 0;
    __syncthreads();

    int pix = blockIdx.x * 256 + t;        // global pixel in [0, B*HW)
    int l = g_is64 ? lblraw[2 * pix] : lblraw[pix];

    unsigned char v;
    if (l == IGN) {
        v = (unsigned char)255;
    } else {
        int k = l < 0 ? 0 : (l > (K_ - 1) ? (K_ - 1) : l);   // clip like ref
        v = (unsigned char)k;
        atomicAdd(&scnt[k], 1);
    }
    g_lbl8[pix] = v;
    __syncthreads();

    if (t < K_ && scnt[t] > 0) {
        int b = (blockIdx.x * 256) / HW_;
        atomicAdd(&g_counts[b * K_ + t], scnt[t]);
    }
}

// ---------------- K3: main — tf32 warp-MMA, cp.async staged feats ----------
// Grid: B_ * SPLITS * CTILES CTAs (ctile fastest -> label L1 reuse), 256 thr.
// Each CTA: 16 channels x 2048 pixels. Per stage: cp.async 16x256 f32 tile
// into padded smem, each of 8 warps MMAs its 32-pixel slice into register
// accumulators D[16ch x 24cls] (3 x m16n8k8 tf32, one-hot B built in regs).
__global__ void __launch_bounds__(256) k_main(const float* __restrict__ feats) {
    __shared__ __align__(16) float tile[16 * ROWPAD];

    const int tid  = threadIdx.x;
    const int lane = tid & 31;
    const int warp = tid >> 5;
    const int g    = lane >> 2;   // groupID: channel row 0..7 (+8)
    const int tig  = lane & 3;    // thread-in-group: pixel col 0..3 (+4)

    int bx    = blockIdx.x;
    const int ctile = bx & (CTILES - 1);       bx >>= 5;
    const int split = bx & (SPLITS - 1);       bx >>= 3;
    const int b     = bx;

    const size_t fbase = ((size_t)(b * C_ + ctile * 16)) * HW_ + (size_t)split * PX_CTA;
    const unsigned char* __restrict__ L =
        g_lbl8 + b * HW_ + split * PX_CTA + warp * 32 + tig;

    float d[3][4] = {{0.f,0.f,0.f,0.f},{0.f,0.f,0.f,0.f},{0.f,0.f,0.f,0.f}};

    for (int s = 0; s < NSTAGES; s++) {
        // ---- stage: global -> smem, fully coalesced (4 x cp.async.cg / thread)
        const float* src = feats + fbase + s * STAGE_PX;
        #pragma unroll
        for (int i = 0; i < 4; i++) {
            int idx = tid + i * 256;          // 0..1023 float4s
            int row = idx >> 6;               // 16 rows
            int q   = idx & 63;               // 64 float4 per row
            uint32_t dst = smem_u32(&tile[row * ROWPAD + q * 4]);
            const float* gsrc = src + (size_t)row * HW_ + q * 4;
            asm volatile("cp.async.cg.shared.global [%0], [%1], 16;"
                         :: "r"(dst), "l"(gsrc));
        }
        asm volatile("cp.async.commit_group;");
        asm volatile("cp.async.wait_group 0;");
        __syncthreads();

        // ---- compute: this warp's 32-pixel slice of the staged tile
        const float* t0 = &tile[g * ROWPAD + warp * 32 + tig];
        const float* t1 = t0 + 8 * ROWPAD;
        const unsigned char* Ls = L + s * STAGE_PX;

        #pragma unroll
        for (int px = 0; px < 32; px += 8) {
            unsigned int l0 = Ls[px];
            unsigned int l1 = Ls[px + 4];
            uint32_t a0, a1, a2, a3;
            asm("cvt.rna.tf32.f32 %0, %1;" : "=r"(a0) : "f"(t0[px]));
            asm("cvt.rna.tf32.f32 %0, %1;" : "=r"(a1) : "f"(t1[px]));
            asm("cvt.rna.tf32.f32 %0, %1;" : "=r"(a2) : "f"(t0[px + 4]));
            asm("cvt.rna.tf32.f32 %0, %1;" : "=r"(a3) : "f"(t1[px + 4]));
            #pragma unroll
            for (int t = 0; t < 3; t++) {
                // B fragment (8px x 8cls, col): b0 = onehot[px=tig][cls=g+8t],
                //                               b1 = onehot[px=tig+4][cls=g+8t]
                uint32_t b0 = (l0 == (unsigned int)(g + 8 * t)) ? 0x3f800000u : 0u;
                uint32_t b1 = (l1 == (unsigned int)(g + 8 * t)) ? 0x3f800000u : 0u;
                asm("mma.sync.aligned.m16n8k8.row.col.f32.tf32.tf32.f32 "
                    "{%0,%1,%2,%3}, {%4,%5,%6,%7}, {%8,%9}, {%0,%1,%2,%3};"
                    : "+f"(d[t][0]), "+f"(d[t][1]), "+f"(d[t][2]), "+f"(d[t][3])
                    : "r"(a0), "r"(a1), "r"(a2), "r"(a3), "r"(b0), "r"(b1));
            }
        }
        __syncthreads();   // all warps done reading before next stage overwrites
    }

    // ---- epilogue: predicated global RED.ADD of the 12 accumulators
    // D mapping: c0/c1 -> (row g,   col 2*tig / 2*tig+1)
    //            c2/c3 -> (row g+8, col 2*tig / 2*tig+1)
    const int cbase = ctile * 16 + g;
    #pragma unroll
    for (int t = 0; t < 3; t++) {
        #pragma unroll
        for (int j = 0; j < 4; j++) {
            int k  = 8 * t + 2 * tig + (j & 1);
            int ch = cbase + ((j >= 2) ? 8 : 0);
            if (k < K_)
                atomicAdd(&g_scratch[((size_t)(b * C_ + ch)) * K_ + k], d[t][j]);
        }
    }
}

// ---------------- K4: finalize — divide by counts, write out [B,C,19,1] ----
__global__ void k_fin(float* __restrict__ out) {
    int i = blockIdx.x * 256 + threadIdx.x;
    if (i >= B_ * C_ * K_) return;
    int k = i % K_;
    int b = i / (C_ * K_);
    int cnt = g_counts[b * K_ + k];
    out[i] = g_scratch[i] / (float)(cnt > 0 ? cnt : 1);
}

// ---------------- launch ----------------
extern "C" void kernel_launch(void* const* d_in, const int* in_sizes, int n_in,
                              void* d_out, int out_size) {
    const float* feats;
    const int*   lbl;
    // metadata order: feats (134217728 elems), gt_seg_map (262144 elems).
    // Be robust to ordering via sizes.
    if (in_sizes[0] > in_sizes[1]) {
        feats = (const float*)d_in[0];
        lbl   = (const int*)d_in[1];
    } else {
        feats = (const float*)d_in[1];
        lbl   = (const int*)d_in[0];
    }

    k_prep0<<<256, 256>>>(lbl);
    k_prep1<<<NPIX / 256, 256>>>(lbl);
    k_main<<<B_ * SPLITS * CTILES, 256>>>(feats);
    k_fin<<<(B_ * C_ * K_ + 255) / 256, 256>>>((float*)d_out);
}

// round 3
// speedup vs baseline: 1.2492x; 1.2492x over previous
#include <cuda_runtime.h>
#include <cstdint>

// Problem constants
#define B_      16
#define C_      512
#define HW_     16384
#define K_      19          // classes
#define IGN     255
#define NPIX    (B_ * HW_)  // 262144
#define OUTN    (B_ * C_ * K_)

// Main-kernel tiling
#define CTILES      (C_ / 16)            // 32 channel tiles of 16
#define SPLITS      8                    // pixel splits -> 2048 px per CTA
#define PX_CTA      (HW_ / SPLITS)       // 2048
#define STAGE_PX    256                  // pixels staged per stage
#define NSTAGES     (PX_CTA / STAGE_PX)  // 8
#define ROWPAD      260                  // 256 + 4 floats pad -> conflict-free LDS

// ---------------- device scratch (no allocations allowed) ----------------
__device__ int            g_is64;
__device__ unsigned char  g_lbl8[NPIX];
__device__ int            g_counts[B_ * K_];

// ---------------- helpers ----------------
__device__ __forceinline__ uint32_t smem_u32(const void* p) {
    uint32_t a;
    asm("{ .reg .u64 t; cvta.to.shared.u64 t, %1; cvt.u32.u64 %0, t; }"
        : "=r"(a) : "l"(p));
    return a;
}

// ---------------- K1: dtype detect + zero out/counts ----------------
__global__ void k_prep0(const int* __restrict__ lblraw, float4* __restrict__ out4) {
    int tid = blockIdx.x * blockDim.x + threadIdx.x;
    int stride = gridDim.x * blockDim.x;

    if (blockIdx.x == 0) {
        // int64 labels (LE, values 0..18) -> every odd 32-bit word of the
        // first 512 elements is 0. For int32 labels: P(all zero) ~ (1/19)^512.
        __shared__ int s_ok;
        if (threadIdx.x == 0) s_ok = 1;
        __syncthreads();
        int bad = 0;
        for (int i = threadIdx.x; i < 512; i += blockDim.x)
            if (lblraw[2 * i + 1] != 0) bad = 1;
        if (bad) atomicAnd(&s_ok, 0);
        __syncthreads();
        if (threadIdx.x == 0) g_is64 = s_ok;
    }

    const float4 z = make_float4(0.f, 0.f, 0.f, 0.f);
    for (int i = tid; i < OUTN / 4; i += stride) out4[i] = z;   // 155648 % 4 == 0
    for (int i = tid; i < B_ * K_; i += stride) g_counts[i] = 0;
}

// ---------------- K2: build u8 labels + per-(b,k) counts ----------------
// One block per 256 pixels; 256 | HW_ so a block stays within one batch b.
__global__ void k_prep1(const int* __restrict__ lblraw) {
    __shared__ int scnt[K_];
    int t = threadIdx.x;
    if (t < K_) scnt[t] = 0;
    __syncthreads();

    int pix = blockIdx.x * 256 + t;
    int l = g_is64 ? lblraw[2 * pix] : lblraw[pix];

    unsigned char v;
    if (l == IGN) {
        v = (unsigned char)255;
    } else {
        int k = l < 0 ? 0 : (l > (K_ - 1) ? (K_ - 1) : l);   // clip like ref
        v = (unsigned char)k;
        atomicAdd(&scnt[k], 1);
    }
    g_lbl8[pix] = v;
    __syncthreads();

    if (t < K_ && scnt[t] > 0) {
        int b = (blockIdx.x * 256) / HW_;
        atomicAdd(&g_counts[b * K_ + t], scnt[t]);
    }
}

// ---------------- K3: main — tf32 warp-MMA, double-buffered cp.async ------
// Grid: B_ * SPLITS * CTILES CTAs (ctile fastest -> label L2 reuse), 256 thr.
// Each CTA: 16 channels x 2048 pixels. Two-stage pipeline: while computing
// stage s from buf[s&1], stage s+1 streams into buf[(s+1)&1].
__global__ void __launch_bounds__(256) k_main(const float* __restrict__ feats,
                                              float* __restrict__ out) {
    __shared__ __align__(16) float tile[2][16 * ROWPAD];   // 2 x 16.6 KB

    const int tid  = threadIdx.x;
    const int lane = tid & 31;
    const int warp = tid >> 5;
    const int g    = lane >> 2;   // channel row 0..7 (+8)
    const int tig  = lane & 3;    // pixel col 0..3 (+4)

    int bx    = blockIdx.x;
    const int ctile = bx & (CTILES - 1);       bx >>= 5;
    const int split = bx & (SPLITS - 1);       bx >>= 3;
    const int b     = bx;

    const size_t fbase = ((size_t)(b * C_ + ctile * 16)) * HW_ + (size_t)split * PX_CTA;
    const unsigned char* __restrict__ L =
        g_lbl8 + b * HW_ + split * PX_CTA + warp * 32 + tig;

    // per-thread stage-load addressing (4 float4s / thread / stage)
    const int lrow = tid >> 6;              // base row for i=0 (rows advance by 4)
    const int lq   = tid & 63;              // float4 within row

    float d[3][4] = {{0.f,0.f,0.f,0.f},{0.f,0.f,0.f,0.f},{0.f,0.f,0.f,0.f}};

    // ---- stage loader: 16 x 256 f32, fully coalesced
    auto load_stage = [&](int s, int buf) {
        const float* src = feats + fbase + s * STAGE_PX;
        #pragma unroll
        for (int i = 0; i < 4; i++) {
            int row = lrow + i * 4;
            uint32_t dst = smem_u32(&tile[buf][row * ROWPAD + lq * 4]);
            const float* gsrc = src + (size_t)row * HW_ + lq * 4;
            asm volatile("cp.async.cg.shared.global [%0], [%1], 16;"
                         :: "r"(dst), "l"(gsrc));
        }
    };

    // prefetch two stages
    load_stage(0, 0);
    asm volatile("cp.async.commit_group;");
    load_stage(1, 1);
    asm volatile("cp.async.commit_group;");

    for (int s = 0; s < NSTAGES; s++) {
        asm volatile("cp.async.wait_group 1;");
        __syncthreads();

        // ---- compute: this warp's 32-pixel slice of buf[s&1]
        const float* t0 = &tile[s & 1][g * ROWPAD + warp * 32 + tig];
        const float* t1 = t0 + 8 * ROWPAD;
        const unsigned char* Ls = L + s * STAGE_PX;

        #pragma unroll
        for (int px = 0; px < 32; px += 8) {
            unsigned int l0 = Ls[px];
            unsigned int l1 = Ls[px + 4];
            uint32_t a0, a1, a2, a3;
            asm("cvt.rna.tf32.f32 %0, %1;" : "=r"(a0) : "f"(t0[px]));
            asm("cvt.rna.tf32.f32 %0, %1;" : "=r"(a1) : "f"(t1[px]));
            asm("cvt.rna.tf32.f32 %0, %1;" : "=r"(a2) : "f"(t0[px + 4]));
            asm("cvt.rna.tf32.f32 %0, %1;" : "=r"(a3) : "f"(t1[px + 4]));
            #pragma unroll
            for (int t = 0; t < 3; t++) {
                uint32_t b0 = (l0 == (unsigned int)(g + 8 * t)) ? 0x3f800000u : 0u;
                uint32_t b1 = (l1 == (unsigned int)(g + 8 * t)) ? 0x3f800000u : 0u;
                asm("mma.sync.aligned.m16n8k8.row.col.f32.tf32.tf32.f32 "
                    "{%0,%1,%2,%3}, {%4,%5,%6,%7}, {%8,%9}, {%0,%1,%2,%3};"
                    : "+f"(d[t][0]), "+f"(d[t][1]), "+f"(d[t][2]), "+f"(d[t][3])
                    : "r"(a0), "r"(a1), "r"(a2), "r"(a3), "r"(b0), "r"(b1));
            }
        }
        __syncthreads();                      // everyone done reading buf[s&1]

        if (s + 2 < NSTAGES) load_stage(s + 2, s & 1);
        asm volatile("cp.async.commit_group;"); // always commit (empty ok)
    }

    // ---- epilogue: cross-warp smem reduction, then scaled RED into d_out
    // All 8 warps hold identical (ch,k) per (slot,lane); sum over warp dim.
    float* red = &tile[0][0];                 // 3072 floats needed, 4160 avail
    #pragma unroll
    for (int t = 0; t < 3; t++)
        #pragma unroll
        for (int j = 0; j < 4; j++)
            red[(t * 4 + j) * 256 + warp * 32 + lane] = d[t][j];
    __syncthreads();

    for (int r = tid; r < 384; r += 256) {
        int slot = r >> 5;                    // 0..11 -> (t, j)
        int ln   = r & 31;
        int t  = slot >> 2, j = slot & 3;
        int gg = ln >> 2,  tg = ln & 3;
        int k  = 8 * t + 2 * tg + (j & 1);
        if (k < K_) {
            float s = 0.f;
            #pragma unroll
            for (int w = 0; w < 8; w++) s += red[slot * 256 + w * 32 + ln];
            int ch  = ctile * 16 + gg + ((j >= 2) ? 8 : 0);
            int cnt = g_counts[b * K_ + k];
            float val = s / (float)(cnt > 0 ? cnt : 1);
            atomicAdd(&out[((size_t)(b * C_ + ch)) * K_ + k], val);
        }
    }
}

// ---------------- launch ----------------
extern "C" void kernel_launch(void* const* d_in, const int* in_sizes, int n_in,
                              void* d_out, int out_size) {
    const float* feats;
    const int*   lbl;
    if (in_sizes[0] > in_sizes[1]) {
        feats = (const float*)d_in[0];
        lbl   = (const int*)d_in[1];
    } else {
        feats = (const float*)d_in[1];
        lbl   = (const int*)d_in[0];
    }

    k_prep0<<<192, 256>>>(lbl, (float4*)d_out);
    k_prep1<<<NPIX / 256, 256>>>(lbl);
    k_main<<<B_ * SPLITS * CTILES, 256>>>(feats, (float*)d_out);
}